// round 16
// baseline (speedup 1.0000x reference)
#include <cuda_runtime.h>
#include <cuda_fp16.h>
#include <cstdint>

// Problem constants
#define DDIM 256
#define HW   1024
#define NN   32768
#define KK   1024
#define NZ   8388608
#define KC   256            // pure fp16: z_hi . e_hi (exactness via refine)
#define GATHER_BLOCKS 1024
#define MAXC 32
#define MARGIN 1.5e-3f      // covers fp16-accum error (>=2*6sigma) with 21x rms slack
#define ESCALE 1024.0f
#define INV2ESCALE (-2.0f / 1024.0f)
#define NKT (KC / 32)       // 8 k-steps
#define NSTG 4              // pipeline stages

// Device scratch (static — no allocations)
__device__ float  g_ek2[KK];
__device__ float  g_zn2[NN];
__device__ float  g_partial[GATHER_BLOCKS];
__device__ __half g_zcat[(size_t)NN * KC];
__device__ __half g_ecat[(size_t)KK * KC];
__device__ int    g_cand[NN][MAXC];
__device__ float  g_cval[NN][MAXC];
__device__ int    g_ccnt[NN];

// ---------------- cp.async helpers ----------------
static __device__ __forceinline__ void cp16s(uint32_t saddr, const void* gsrc) {
    asm volatile("cp.async.cg.shared.global [%0], [%1], 16;" :: "r"(saddr), "l"(gsrc));
}
static __device__ __forceinline__ void cp_commit() {
    asm volatile("cp.async.commit_group;");
}
template <int N>
static __device__ __forceinline__ void cp_wait() {
    asm volatile("cp.async.wait_group %0;" :: "n"(N));
}
static __device__ __forceinline__ uint32_t smaddr(const void* p) {
    return (uint32_t)__cvta_generic_to_shared(p);
}

// ---------------- mma helpers ----------------
static __device__ __forceinline__ void ldsm4(unsigned& r0, unsigned& r1,
                                             unsigned& r2, unsigned& r3, unsigned a) {
    asm volatile("ldmatrix.sync.aligned.m8n8.x4.shared.b16 {%0,%1,%2,%3}, [%4];"
                 : "=r"(r0), "=r"(r1), "=r"(r2), "=r"(r3) : "r"(a));
}
// fp16-accumulate HMMA: c/d are 2 regs of packed halves
static __device__ __forceinline__ void mma16816h(unsigned* c, const unsigned* a,
                                                 const unsigned* b) {
    asm volatile(
        "mma.sync.aligned.m16n8k16.row.col.f16.f16.f16.f16 "
        "{%0,%1}, {%2,%3,%4,%5}, {%6,%7}, {%0,%1};"
        : "+r"(c[0]), "+r"(c[1])
        : "r"(a[0]), "r"(a[1]), "r"(a[2]), "r"(a[3]), "r"(b[0]), "r"(b[1]));
}

// ---------------- kernel A: splite + ek2 (one emb pass) ----------------
__global__ void splite_ek2_kernel(const float* __restrict__ emb) {
    int k    = blockIdx.x * 8 + (threadIdx.x >> 5);
    int lane = threadIdx.x & 31;
    const float* row = emb + (size_t)k * DDIM;
    __half* B = g_ecat + (size_t)k * KC;
    float s = 0.f;
#pragma unroll
    for (int i = 0; i < 8; ++i) {
        float v = row[lane + 32 * i];
        B[lane + 32 * i] = __float2half_rn(v * ESCALE);
        s = fmaf(v, v, s);
    }
#pragma unroll
    for (int o = 16; o; o >>= 1) s += __shfl_down_sync(0xffffffffu, s, o);
    if (lane == 0) g_ek2[k] = s;
}

// ---------------- kernel P: transpose + fp16(z) + zn2 + ccnt zero -----------
__global__ void __launch_bounds__(256)
prep_kernel(const float* __restrict__ z) {
    __shared__ float sm[DDIM][33];

    const int tid = threadIdx.x;
    const int n0  = blockIdx.x * 32;
    const int b   = n0 >> 10;
    const int hw0 = n0 & 1023;
    const float* zp = z + (size_t)b * (DDIM * HW) + hw0;

    const int lane = tid & 31;
    const int dg   = tid >> 5;
#pragma unroll 8
    for (int it = 0; it < 32; ++it) {
        int d = dg + it * 8;
        sm[d][lane] = zp[(size_t)d * HW + lane];
    }
    __syncthreads();

    if (tid < 32) {
        g_ccnt[n0 + tid] = 0;
        float acc = 0.f;
#pragma unroll 8
        for (int d = 0; d < DDIM; ++d) {
            float v = sm[d][tid];
            acc = __fadd_rn(acc, __fmul_rn(v, v));
        }
        g_zn2[n0 + tid] = acc;
    }

    const int n  = tid >> 3;
    const int dq = tid & 7;
    const int d0 = dq * 32;
    __half2 hb[16];
#pragma unroll
    for (int j = 0; j < 16; ++j) {
        hb[j] = __halves2half2(__float2half_rn(sm[d0 + 2 * j][n]),
                               __float2half_rn(sm[d0 + 2 * j + 1][n]));
    }
    __half* A = g_zcat + (size_t)(n0 + n) * KC;
#pragma unroll
    for (int q = 0; q < 4; ++q)
        *(float4*)(A + d0 + 8 * q) = *(float4*)&hb[4 * q];
}

// ---------------- kernel G: HMMA GEMM (fp16 accum) + fused epilogue ---------
// CTA: 128m x 128n, 8 warps = 2(m) x 4(n), warp 64m x 32n, K-stage 32,
// 4-stage cp.async pipeline, one barrier per k-step; fp16 accumulators.
#define STG_BYTES 8192
#define SMB_B (NSTG * STG_BYTES)
#define SMB_MIN (2 * NSTG * STG_BYTES)
#define SM_DYN (2 * NSTG * STG_BYTES + 2048 + 1024)

__global__ void __launch_bounds__(256, 2)
vq_gemm_kernel() {
    extern __shared__ __align__(16) char dyn[];
    uint32_t raw  = (uint32_t)__cvta_generic_to_shared(dyn);
    uint32_t base = (raw + 1023) & ~1023u;
    char*    smg  = dyn + (base - raw);
    float*   smin = (float*)(smg + SMB_MIN);      // [128][4]

    const int tid  = threadIdx.x;
    const int w    = tid >> 5;
    const int lane = tid & 31;
    const int wm   = (w & 1) * 64;
    const int wn   = (w >> 1) * 32;
    const int m0   = blockIdx.x * 128;
    const int n0   = blockIdx.y * 128;

    unsigned c[4][4][2];                // fp16x2 accumulators
#pragma unroll
    for (int ms = 0; ms < 4; ++ms)
#pragma unroll
        for (int ns = 0; ns < 4; ++ns) { c[ms][ns][0] = 0u; c[ms][ns][1] = 0u; }

    auto sAddr = [&](uint32_t arr, int buf, int row, int seg) -> uint32_t {
        return base + arr + buf * STG_BYTES + row * 64 + (((unsigned)(seg ^ (row & 3))) << 4);
    };

    auto loadStage = [&](int kt, int buf) {
        const int kc0 = kt * 32;
#pragma unroll
        for (int r = 0; r < 2; ++r) {
            int i = tid + 256 * r;
            int row = i >> 2;
            int seg = i & 3;
            cp16s(sAddr(0, buf, row, seg),
                  g_zcat + (size_t)(m0 + row) * KC + kc0 + seg * 8);
            cp16s(sAddr(SMB_B, buf, row, seg),
                  g_ecat + (size_t)(n0 + row) * KC + kc0 + seg * 8);
        }
    };

#pragma unroll
    for (int s = 0; s < NSTG - 1; ++s) { loadStage(s, s); cp_commit(); }

#pragma unroll 1
    for (int kt = 0; kt < NKT; ++kt) {
        cp_wait<NSTG - 2>();
        __syncthreads();

        if (kt + NSTG - 1 < NKT) loadStage(kt + NSTG - 1, (kt + NSTG - 1) & (NSTG - 1));
        cp_commit();

        const int buf = kt & (NSTG - 1);
#pragma unroll
        for (int kh = 0; kh < 2; ++kh) {
            unsigned a[4][4], b[4][2];
#pragma unroll
            for (int ms = 0; ms < 4; ++ms) {
                int row = wm + ms * 16 + (lane & 15);
                int seg = kh * 2 + (lane >> 4);
                ldsm4(a[ms][0], a[ms][1], a[ms][2], a[ms][3], sAddr(0, buf, row, seg));
            }
#pragma unroll
            for (int np = 0; np < 2; ++np) {
                int row = wn + np * 16 + (lane & 15);
                int seg = kh * 2 + (lane >> 4);
                unsigned r0, r1, r2, r3;
                ldsm4(r0, r1, r2, r3, sAddr(SMB_B, buf, row, seg));
                b[2 * np][0] = r0;     b[2 * np][1] = r2;
                b[2 * np + 1][0] = r1; b[2 * np + 1][1] = r3;
            }
#pragma unroll
            for (int ms = 0; ms < 4; ++ms)
#pragma unroll
                for (int ns = 0; ns < 4; ++ns)
                    mma16816h(c[ms][ns], a[ms], b[ns]);
        }
    }

    // ---- fused epilogue ----
    const int gid = lane >> 2;
    const int tg  = lane & 3;

    // unpack fp16 accums -> adist floats
    float f[4][4][4];
#pragma unroll
    for (int ns = 0; ns < 4; ++ns) {
        int col = n0 + wn + ns * 8 + tg * 2;
        float e0 = g_ek2[col], e1 = g_ek2[col + 1];
#pragma unroll
        for (int ms = 0; ms < 4; ++ms) {
            __half2 h01 = *(__half2*)&c[ms][ns][0];   // row gid,   cols (0,1)
            __half2 h23 = *(__half2*)&c[ms][ns][1];   // row gid+8, cols (0,1)
            f[ms][ns][0] = fmaf(INV2ESCALE, __half2float(__low2half(h01)),  e0);
            f[ms][ns][1] = fmaf(INV2ESCALE, __half2float(__high2half(h01)), e1);
            f[ms][ns][2] = fmaf(INV2ESCALE, __half2float(__low2half(h23)),  e0);
            f[ms][ns][3] = fmaf(INV2ESCALE, __half2float(__high2half(h23)), e1);
        }
    }

    __syncthreads();

    // per-row warp-slice min (8 local values, quad shuffle)
#pragma unroll
    for (int ms = 0; ms < 4; ++ms) {
#pragma unroll
        for (int h = 0; h < 2; ++h) {
            float r = f[ms][0][2 * h];
#pragma unroll
            for (int ns = 0; ns < 4; ++ns) {
                r = fminf(r, f[ms][ns][2 * h]);
                r = fminf(r, f[ms][ns][2 * h + 1]);
            }
            r = fminf(r, __shfl_xor_sync(0xffffffffu, r, 1));
            r = fminf(r, __shfl_xor_sync(0xffffffffu, r, 2));
            if (tg == 0) smin[(wm + ms * 16 + gid + 8 * h) * 4 + (w >> 1)] = r;
        }
    }
    __syncthreads();

    // candidate append: v <= ctamin(row) + MARGIN
#pragma unroll
    for (int ms = 0; ms < 4; ++ms) {
#pragma unroll
        for (int h = 0; h < 2; ++h) {
            int row = wm + ms * 16 + gid + 8 * h;
            float thr = fminf(fminf(smin[row * 4], smin[row * 4 + 1]),
                              fminf(smin[row * 4 + 2], smin[row * 4 + 3])) + MARGIN;
            int n = m0 + row;
#pragma unroll
            for (int ns = 0; ns < 4; ++ns) {
#pragma unroll
                for (int e = 0; e < 2; ++e) {
                    float v = f[ms][ns][2 * h + e];
                    if (v <= thr) {
                        int slot = atomicAdd(&g_ccnt[n], 1);
                        if (slot < MAXC) {
                            g_cand[n][slot] = n0 + wn + ns * 8 + tg * 2 + e;
                            g_cval[n][slot] = v;
                        }
                    }
                }
            }
        }
    }
}

// ---------------- kernel T: fused refine + gather + idx output --------------
// One block per 32 rows (256 thr — R14 config). cp.async z tile; exact chains
// (bit-exact Eigen order); two-half emb staging; shuffle loss reduction.
#define FUSED_SMEM 56320
__global__ void __launch_bounds__(256)
fused_tail_kernel(const float* __restrict__ z, const float* __restrict__ emb,
                  float* __restrict__ out, int write_idx) {
    extern __shared__ float smf[];
    float* zt    = smf;                       // [256][36]
    float* rows  = zt + 256 * 36;             // [32][129]
    float* jdist = rows + 32 * 129;           // [192]
    float* red   = jdist + 192;               // [8]
    int*   sidx  = (int*)(red + 8);           // [32]
    int*   sfc   = sidx + 32;                 // [32]
    int*   jbase = sfc + 32;                  // [32]
    int*   jrow  = jbase + 32;                // [192]
    int*   jk    = jrow + 192;                // [192]
    int*   njobs = jk + 192;                  // [1]

    const int tid = threadIdx.x;
    const int n0  = blockIdx.x * 32;
    const int b   = n0 >> 10;
    const int hw0 = n0 & 1023;
    const float* zp = z + (size_t)b * (DDIM * HW) + hw0;

    if (tid == 0) *njobs = 0;

    // P1: async stage z tile (256 rows x 32 floats)
#pragma unroll
    for (int r = 0; r < 8; ++r) {
        int i = tid + 256 * r;
        int d = i >> 3, m = i & 7;
        cp16s(smaddr(&zt[d * 36 + 4 * m]), zp + (size_t)d * HW + 4 * m);
    }
    cp_commit();

    // P2: per-row candidate filter (warp 0) — overlapped with z loads
    if (tid < 32) {
        __syncwarp();
        int n = n0 + tid;
        int cnt = g_ccnt[n];
        bool full = (cnt > MAXC);
        int cl = full ? 0 : cnt;
        float gmin = 3.4e38f;
        for (int s2 = 0; s2 < cl; ++s2) gmin = fminf(gmin, g_cval[n][s2]);
        float thr = gmin + MARGIN;
        int fk[6];
        int fc = 0;
        for (int s2 = 0; s2 < cl; ++s2) {
            if (g_cval[n][s2] <= thr) {
                if (fc < 6) fk[fc] = g_cand[n][s2];
                fc++;
            }
        }
        if (fc > 6) { full = true; fc = 0; }

        if (!full && fc == 1) {
            sidx[tid] = fk[0];      // proven unique argmin (margin bound)
            sfc[tid]  = 1;
        } else if (full) {
            sfc[tid] = -1;          // full-scan fallback
        } else {
            sfc[tid] = fc;
            int base = atomicAdd(njobs, fc);
            jbase[tid] = base;
            for (int s2 = 0; s2 < fc; ++s2) { jrow[base + s2] = tid; jk[base + s2] = fk[s2]; }
        }
    }
    cp_wait<0>();
    __syncthreads();

    // P3: exact chains (one per job); z from smem column, ascending d
    {
        int nj = *njobs;
        if (tid < nj) {
            int row = jrow[tid], k = jk[tid];
            const float4* e4 = (const float4*)(emb + (size_t)k * DDIM);
            float acc = 0.f;
#pragma unroll 8
            for (int q = 0; q < DDIM / 4; ++q) {
                float4 v = e4[q];
                acc = fmaf(zt[(4 * q)     * 36 + row], v.x, acc);
                acc = fmaf(zt[(4 * q + 1) * 36 + row], v.y, acc);
                acc = fmaf(zt[(4 * q + 2) * 36 + row], v.z, acc);
                acc = fmaf(zt[(4 * q + 3) * 36 + row], v.w, acc);
            }
            jdist[tid] = fmaf(-2.f, acc, __fadd_rn(g_zn2[n0 + row], g_ek2[k]));
        }
    }
    __syncthreads();

    // P4: exact select (lowest-index ties) + rare full-scan fallback + idx out
    if (tid < 32) {
        int fc = sfc[tid];
        if (fc >= 2) {
            int base = jbase[tid];
            float bv = 3.4e38f; int bi = 0;
            for (int s2 = 0; s2 < fc; ++s2) {
                float dv = jdist[base + s2];
                int   kv = jk[base + s2];
                if (dv < bv || (dv == bv && kv < bi)) { bv = dv; bi = kv; }
            }
            sidx[tid] = bi;
        } else if (fc == -1) {      // astronomically rare
            float zn = g_zn2[n0 + tid];
            float bv = 3.4e38f; int bi = 0;
            for (int k = 0; k < KK; ++k) {
                const float* ep = emb + (size_t)k * DDIM;
                float acc = 0.f;
#pragma unroll 8
                for (int d = 0; d < DDIM; ++d)
                    acc = fmaf(zt[d * 36 + tid], ep[d], acc);
                float dist = fmaf(-2.f, acc, __fadd_rn(zn, g_ek2[k]));
                if (dist < bv) { bv = dist; bi = k; }
            }
            sidx[tid] = bi;
        }
        if (write_idx) out[NZ + 1 + n0 + tid] = (float)sidx[tid];
    }

    // P5/P6: emb rows staged in two 128-d halves; straight-through + loss
    const int j  = tid & 31;
    const int ds = tid >> 5;
    float s = 0.f;
    float* op = out + (size_t)b * (DDIM * HW) + hw0 + j;
#pragma unroll
    for (int half = 0; half < 2; ++half) {
        __syncthreads();   // rows free; sidx visible (half 0)
#pragma unroll
        for (int r = 0; r < 4; ++r) {
            int i4  = tid + 256 * r;
            int row = i4 >> 5;
            int c4  = (i4 & 31) << 2;
            float4 v = *(const float4*)(emb + (size_t)sidx[row] * DDIM + 128 * half + c4);
            rows[row * 129 + c4]     = v.x;
            rows[row * 129 + c4 + 1] = v.y;
            rows[row * 129 + c4 + 2] = v.z;
            rows[row * 129 + c4 + 3] = v.w;
        }
        __syncthreads();
#pragma unroll 8
        for (int pass = 0; pass < 16; ++pass) {
            int dl = pass * 8 + ds;
            int d  = 128 * half + dl;
            float q  = rows[j * 129 + dl];
            float zv = zt[d * 36 + j];
            float df = __fadd_rn(q, -zv);
            op[(size_t)d * HW] = __fadd_rn(zv, df);
            s = fmaf(df, df, s);
        }
    }

    // loss partial: warp shuffle + 8-slot smem reduce (deterministic)
#pragma unroll
    for (int o = 16; o; o >>= 1) s += __shfl_down_sync(0xffffffffu, s, o);
    if ((tid & 31) == 0) red[tid >> 5] = s;
    __syncthreads();
    if (tid == 0) {
        float t = red[0];
#pragma unroll
        for (int q = 1; q < 8; ++q) t += red[q];
        g_partial[blockIdx.x] = t;
    }
}

// ---------------- kernel D: finalize loss ----------------
__global__ void finalize_kernel(float* __restrict__ out) {
    __shared__ float red[256];
    float s = 0.f;
#pragma unroll
    for (int r = 0; r < GATHER_BLOCKS / 256; ++r)
        s += g_partial[threadIdx.x + 256 * r];
    red[threadIdx.x] = s;
    __syncthreads();
#pragma unroll
    for (int o = 128; o; o >>= 1) {
        if (threadIdx.x < o) red[threadIdx.x] += red[threadIdx.x + o];
        __syncthreads();
    }
    if (threadIdx.x == 0) {
        float q = red[0] / (float)NZ;
        out[NZ] = __fadd_rn(q, 0.25f * q);
    }
}

extern "C" void kernel_launch(void* const* d_in, const int* in_sizes, int n_in,
                              void* d_out, int out_size) {
    const float* a0 = (const float*)d_in[0];
    const float* a1 = (const float*)d_in[1];
    const float* z;
    const float* emb;
    if (in_sizes[0] == NZ) { z = a0; emb = a1; }
    else                   { z = a1; emb = a0; }
    float* out = (float*)d_out;

    cudaFuncSetAttribute(vq_gemm_kernel,
                         cudaFuncAttributeMaxDynamicSharedMemorySize, SM_DYN);
    cudaFuncSetAttribute(fused_tail_kernel,
                         cudaFuncAttributeMaxDynamicSharedMemorySize, FUSED_SMEM);

    int write_idx = (out_size >= NZ + 1 + NN) ? 1 : 0;

    splite_ek2_kernel<<<128, 256>>>(emb);
    prep_kernel<<<NN / 32, 256>>>(z);
    vq_gemm_kernel<<<dim3(256, 8), 256, SM_DYN>>>();
    fused_tail_kernel<<<GATHER_BLOCKS, 256, FUSED_SMEM>>>(z, emb, out, write_idx);
    if (out_size > NZ) finalize_kernel<<<1, 256>>>(out);
}

// round 17
// speedup vs baseline: 37.0249x; 37.0249x over previous
#include <cuda_runtime.h>
#include <cuda_fp16.h>
#include <cstdint>

// Problem constants
#define DDIM 256
#define HW   1024
#define NN   32768
#define KK   1024
#define NZ   8388608
#define KC   256            // pure fp16: z_hi . e_hi (exactness via refine)
#define GATHER_BLOCKS 1024
#define MAXC 32
#define MARGIN 4e-4f
#define ESCALE 1024.0f
#define INV2ESCALE (-2.0f / 1024.0f)
#define NKT (KC / 32)       // 8 k-steps
#define NSTG 4              // pipeline stages

// Device scratch (static — no allocations)
__device__ float  g_ek2[KK];
__device__ float  g_zn2[NN];
__device__ float  g_partial[GATHER_BLOCKS];
__device__ __half g_zcat[(size_t)NN * KC];
__device__ __half g_ecat[(size_t)KK * KC];
__device__ int    g_cand[NN][MAXC];
__device__ float  g_cval[NN][MAXC];
__device__ int    g_ccnt[NN];

// ---------------- cp.async helpers ----------------
static __device__ __forceinline__ void cp16s(uint32_t saddr, const void* gsrc) {
    asm volatile("cp.async.cg.shared.global [%0], [%1], 16;" :: "r"(saddr), "l"(gsrc));
}
static __device__ __forceinline__ void cp_commit() {
    asm volatile("cp.async.commit_group;");
}
template <int N>
static __device__ __forceinline__ void cp_wait() {
    asm volatile("cp.async.wait_group %0;" :: "n"(N));
}
static __device__ __forceinline__ uint32_t smaddr(const void* p) {
    return (uint32_t)__cvta_generic_to_shared(p);
}

// ---------------- mma helpers ----------------
static __device__ __forceinline__ void ldsm4(unsigned& r0, unsigned& r1,
                                             unsigned& r2, unsigned& r3, unsigned a) {
    asm volatile("ldmatrix.sync.aligned.m8n8.x4.shared.b16 {%0,%1,%2,%3}, [%4];"
                 : "=r"(r0), "=r"(r1), "=r"(r2), "=r"(r3) : "r"(a));
}
static __device__ __forceinline__ void mma16816(float* c, const unsigned* a,
                                                const unsigned* b) {
    asm volatile(
        "mma.sync.aligned.m16n8k16.row.col.f32.f16.f16.f32 "
        "{%0,%1,%2,%3}, {%4,%5,%6,%7}, {%8,%9}, {%0,%1,%2,%3};"
        : "+f"(c[0]), "+f"(c[1]), "+f"(c[2]), "+f"(c[3])
        : "r"(a[0]), "r"(a[1]), "r"(a[2]), "r"(a[3]), "r"(b[0]), "r"(b[1]));
}

// ---------------- kernel P: fused prep ----------------
// Blocks [0,1024): z transpose + fp16 split + zn2 + ccnt zero (cp.async-staged).
// Blocks [1024,1152): emb split + ek2 (one emb pass, 8 warps = 8 k-rows).
#define PREP_SMEM (256 * 36 * 4)
__global__ void __launch_bounds__(256)
prep_kernel(const float* __restrict__ z, const float* __restrict__ emb) {
    extern __shared__ float zt[];             // [256][36] (16B-aligned rows)
    const int tid = threadIdx.x;

    if (blockIdx.x >= GATHER_BLOCKS) {
        // ---- splite + ek2 ----
        int k    = (blockIdx.x - GATHER_BLOCKS) * 8 + (tid >> 5);
        int lane = tid & 31;
        const float* row = emb + (size_t)k * DDIM;
        __half* B = g_ecat + (size_t)k * KC;
        float s = 0.f;
#pragma unroll
        for (int i = 0; i < 8; ++i) {
            float v = row[lane + 32 * i];
            B[lane + 32 * i] = __float2half_rn(v * ESCALE);
            s = fmaf(v, v, s);
        }
#pragma unroll
        for (int o = 16; o; o >>= 1) s += __shfl_down_sync(0xffffffffu, s, o);
        if (lane == 0) g_ek2[k] = s;
        return;
    }

    const int n0  = blockIdx.x * 32;
    const int b   = n0 >> 10;
    const int hw0 = n0 & 1023;
    const float* zp = z + (size_t)b * (DDIM * HW) + hw0;

    // async stage z tile (256 d-rows x 32 n-cols)
#pragma unroll
    for (int r = 0; r < 8; ++r) {
        int i = tid + 256 * r;
        int d = i >> 3, m = i & 7;
        cp16s(smaddr(&zt[d * 36 + 4 * m]), zp + (size_t)d * HW + 4 * m);
    }
    cp_commit();
    cp_wait<0>();
    __syncthreads();

    if (tid < 32) {
        g_ccnt[n0 + tid] = 0;
        float acc = 0.f;
#pragma unroll 8
        for (int d = 0; d < DDIM; ++d) {
            float v = zt[d * 36 + tid];
            acc = __fadd_rn(acc, __fmul_rn(v, v));   // exact XLA order
        }
        g_zn2[n0 + tid] = acc;
    }

    const int n  = tid >> 3;
    const int dq = tid & 7;
    const int d0 = dq * 32;
    __half2 hb[16];
#pragma unroll
    for (int j = 0; j < 16; ++j) {
        hb[j] = __halves2half2(__float2half_rn(zt[(d0 + 2 * j) * 36 + n]),
                               __float2half_rn(zt[(d0 + 2 * j + 1) * 36 + n]));
    }
    __half* A = g_zcat + (size_t)(n0 + n) * KC;
#pragma unroll
    for (int q = 0; q < 4; ++q)
        *(float4*)(A + d0 + 8 * q) = *(float4*)&hb[4 * q];
}

// ---------------- kernel G: HMMA GEMM + fused min/candidate epilogue --------
// (exact R14 configuration: fp32 accum, 128m x 128n, 4-stage pipeline)
#define STG_BYTES 8192
#define SMB_B (NSTG * STG_BYTES)
#define SMB_MIN (2 * NSTG * STG_BYTES)
#define SM_DYN (2 * NSTG * STG_BYTES + 2048 + 1024)

__global__ void __launch_bounds__(256, 2)
vq_gemm_kernel() {
    extern __shared__ __align__(16) char dyn[];
    uint32_t raw  = (uint32_t)__cvta_generic_to_shared(dyn);
    uint32_t base = (raw + 1023) & ~1023u;
    char*    smg  = dyn + (base - raw);
    float*   smin = (float*)(smg + SMB_MIN);      // [128][4]

    const int tid  = threadIdx.x;
    const int w    = tid >> 5;
    const int lane = tid & 31;
    const int wm   = (w & 1) * 64;
    const int wn   = (w >> 1) * 32;
    const int m0   = blockIdx.x * 128;
    const int n0   = blockIdx.y * 128;

    float c[4][4][4];
#pragma unroll
    for (int ms = 0; ms < 4; ++ms)
#pragma unroll
        for (int ns = 0; ns < 4; ++ns)
#pragma unroll
            for (int q = 0; q < 4; ++q) c[ms][ns][q] = 0.f;

    auto sAddr = [&](uint32_t arr, int buf, int row, int seg) -> uint32_t {
        return base + arr + buf * STG_BYTES + row * 64 + (((unsigned)(seg ^ (row & 3))) << 4);
    };

    auto loadStage = [&](int kt, int buf) {
        const int kc0 = kt * 32;
#pragma unroll
        for (int r = 0; r < 2; ++r) {
            int i = tid + 256 * r;
            int row = i >> 2;
            int seg = i & 3;
            cp16s(sAddr(0, buf, row, seg),
                  g_zcat + (size_t)(m0 + row) * KC + kc0 + seg * 8);
            cp16s(sAddr(SMB_B, buf, row, seg),
                  g_ecat + (size_t)(n0 + row) * KC + kc0 + seg * 8);
        }
    };

#pragma unroll
    for (int s = 0; s < NSTG - 1; ++s) { loadStage(s, s); cp_commit(); }

#pragma unroll 1
    for (int kt = 0; kt < NKT; ++kt) {
        cp_wait<NSTG - 2>();
        __syncthreads();

        if (kt + NSTG - 1 < NKT) loadStage(kt + NSTG - 1, (kt + NSTG - 1) & (NSTG - 1));
        cp_commit();

        const int buf = kt & (NSTG - 1);
#pragma unroll
        for (int kh = 0; kh < 2; ++kh) {
            unsigned a[4][4], b[4][2];
#pragma unroll
            for (int ms = 0; ms < 4; ++ms) {
                int row = wm + ms * 16 + (lane & 15);
                int seg = kh * 2 + (lane >> 4);
                ldsm4(a[ms][0], a[ms][1], a[ms][2], a[ms][3], sAddr(0, buf, row, seg));
            }
#pragma unroll
            for (int np = 0; np < 2; ++np) {
                int row = wn + np * 16 + (lane & 15);
                int seg = kh * 2 + (lane >> 4);
                unsigned r0, r1, r2, r3;
                ldsm4(r0, r1, r2, r3, sAddr(SMB_B, buf, row, seg));
                b[2 * np][0] = r0;     b[2 * np][1] = r2;
                b[2 * np + 1][0] = r1; b[2 * np + 1][1] = r3;
            }
#pragma unroll
            for (int ms = 0; ms < 4; ++ms)
#pragma unroll
                for (int ns = 0; ns < 4; ++ns)
                    mma16816(c[ms][ns], a[ms], b[ns]);
        }
    }

    // ---- fused epilogue ----
    const int gid = lane >> 2;
    const int tg  = lane & 3;

#pragma unroll
    for (int ns = 0; ns < 4; ++ns) {
        int col = n0 + wn + ns * 8 + tg * 2;
        float e0 = g_ek2[col], e1 = g_ek2[col + 1];
#pragma unroll
        for (int ms = 0; ms < 4; ++ms) {
            c[ms][ns][0] = fmaf(INV2ESCALE, c[ms][ns][0], e0);
            c[ms][ns][1] = fmaf(INV2ESCALE, c[ms][ns][1], e1);
            c[ms][ns][2] = fmaf(INV2ESCALE, c[ms][ns][2], e0);
            c[ms][ns][3] = fmaf(INV2ESCALE, c[ms][ns][3], e1);
        }
    }

    __syncthreads();

#pragma unroll
    for (int ms = 0; ms < 4; ++ms) {
#pragma unroll
        for (int h = 0; h < 2; ++h) {
            float r = c[ms][0][2 * h];
#pragma unroll
            for (int ns = 0; ns < 4; ++ns) {
                r = fminf(r, c[ms][ns][2 * h]);
                r = fminf(r, c[ms][ns][2 * h + 1]);
            }
            r = fminf(r, __shfl_xor_sync(0xffffffffu, r, 1));
            r = fminf(r, __shfl_xor_sync(0xffffffffu, r, 2));
            if (tg == 0) smin[(wm + ms * 16 + gid + 8 * h) * 4 + (w >> 1)] = r;
        }
    }
    __syncthreads();

#pragma unroll
    for (int ms = 0; ms < 4; ++ms) {
#pragma unroll
        for (int h = 0; h < 2; ++h) {
            int row = wm + ms * 16 + gid + 8 * h;
            float thr = fminf(fminf(smin[row * 4], smin[row * 4 + 1]),
                              fminf(smin[row * 4 + 2], smin[row * 4 + 3])) + MARGIN;
            int n = m0 + row;
#pragma unroll
            for (int ns = 0; ns < 4; ++ns) {
#pragma unroll
                for (int e = 0; e < 2; ++e) {
                    float v = c[ms][ns][2 * h + e];
                    if (v <= thr) {
                        int slot = atomicAdd(&g_ccnt[n], 1);
                        if (slot < MAXC) {
                            g_cand[n][slot] = n0 + wn + ns * 8 + tg * 2 + e;
                            g_cval[n][slot] = v;
                        }
                    }
                }
            }
        }
    }
}

// ---------------- kernel T: fused refine + gather + idx output --------------
// (exact R14 configuration: 256 threads, 32 rows/block)
#define FUSED_SMEM 56320
__global__ void __launch_bounds__(256)
fused_tail_kernel(const float* __restrict__ z, const float* __restrict__ emb,
                  float* __restrict__ out, int write_idx) {
    extern __shared__ float smf[];
    float* zt    = smf;                       // [256][36]
    float* rows  = zt + 256 * 36;             // [32][129]
    float* jdist = rows + 32 * 129;           // [192]
    float* red   = jdist + 192;               // [8]
    int*   sidx  = (int*)(red + 8);           // [32]
    int*   sfc   = sidx + 32;                 // [32]
    int*   jbase = sfc + 32;                  // [32]
    int*   jrow  = jbase + 32;                // [192]
    int*   jk    = jrow + 192;                // [192]
    int*   njobs = jk + 192;                  // [1]

    const int tid = threadIdx.x;
    const int n0  = blockIdx.x * 32;
    const int b   = n0 >> 10;
    const int hw0 = n0 & 1023;
    const float* zp = z + (size_t)b * (DDIM * HW) + hw0;

    if (tid == 0) *njobs = 0;

    // P1: async stage z tile
#pragma unroll
    for (int r = 0; r < 8; ++r) {
        int i = tid + 256 * r;
        int d = i >> 3, m = i & 7;
        cp16s(smaddr(&zt[d * 36 + 4 * m]), zp + (size_t)d * HW + 4 * m);
    }
    cp_commit();

    // P2: per-row candidate filter (warp 0) — overlapped with z loads
    if (tid < 32) {
        __syncwarp();
        int n = n0 + tid;
        int cnt = g_ccnt[n];
        bool full = (cnt > MAXC);
        int cl = full ? 0 : cnt;
        float gmin = 3.4e38f;
        for (int s2 = 0; s2 < cl; ++s2) gmin = fminf(gmin, g_cval[n][s2]);
        float thr = gmin + MARGIN;
        int fk[6];
        int fc = 0;
        for (int s2 = 0; s2 < cl; ++s2) {
            if (g_cval[n][s2] <= thr) {
                if (fc < 6) fk[fc] = g_cand[n][s2];
                fc++;
            }
        }
        if (fc > 6) { full = true; fc = 0; }

        if (!full && fc == 1) {
            sidx[tid] = fk[0];      // proven unique argmin (margin bound)
            sfc[tid]  = 1;
        } else if (full) {
            sfc[tid] = -1;          // full-scan fallback
        } else {
            sfc[tid] = fc;
            int base = atomicAdd(njobs, fc);
            jbase[tid] = base;
            for (int s2 = 0; s2 < fc; ++s2) { jrow[base + s2] = tid; jk[base + s2] = fk[s2]; }
        }
    }
    cp_wait<0>();
    __syncthreads();

    // P3: exact chains (one per job); z from smem column, ascending d
    {
        int nj = *njobs;
        if (tid < nj) {
            int row = jrow[tid], k = jk[tid];
            const float4* e4 = (const float4*)(emb + (size_t)k * DDIM);
            float acc = 0.f;
#pragma unroll 8
            for (int q = 0; q < DDIM / 4; ++q) {
                float4 v = e4[q];
                acc = fmaf(zt[(4 * q)     * 36 + row], v.x, acc);
                acc = fmaf(zt[(4 * q + 1) * 36 + row], v.y, acc);
                acc = fmaf(zt[(4 * q + 2) * 36 + row], v.z, acc);
                acc = fmaf(zt[(4 * q + 3) * 36 + row], v.w, acc);
            }
            jdist[tid] = fmaf(-2.f, acc, __fadd_rn(g_zn2[n0 + row], g_ek2[k]));
        }
    }
    __syncthreads();

    // P4: exact select (lowest-index ties) + rare full-scan fallback + idx out
    if (tid < 32) {
        int fc = sfc[tid];
        if (fc >= 2) {
            int base = jbase[tid];
            float bv = 3.4e38f; int bi = 0;
            for (int s2 = 0; s2 < fc; ++s2) {
                float dv = jdist[base + s2];
                int   kv = jk[base + s2];
                if (dv < bv || (dv == bv && kv < bi)) { bv = dv; bi = kv; }
            }
            sidx[tid] = bi;
        } else if (fc == -1) {      // astronomically rare
            float zn = g_zn2[n0 + tid];
            float bv = 3.4e38f; int bi = 0;
            for (int k = 0; k < KK; ++k) {
                const float* ep = emb + (size_t)k * DDIM;
                float acc = 0.f;
#pragma unroll 8
                for (int d = 0; d < DDIM; ++d)
                    acc = fmaf(zt[d * 36 + tid], ep[d], acc);
                float dist = fmaf(-2.f, acc, __fadd_rn(zn, g_ek2[k]));
                if (dist < bv) { bv = dist; bi = k; }
            }
            sidx[tid] = bi;
        }
        if (write_idx) out[NZ + 1 + n0 + tid] = (float)sidx[tid];
    }

    // P5/P6: emb rows staged in two 128-d halves; straight-through + loss
    const int j  = tid & 31;
    const int ds = tid >> 5;
    float s = 0.f;
    float* op = out + (size_t)b * (DDIM * HW) + hw0 + j;
#pragma unroll
    for (int half = 0; half < 2; ++half) {
        __syncthreads();   // rows free; sidx visible (half 0)
#pragma unroll
        for (int r = 0; r < 4; ++r) {
            int i4  = tid + 256 * r;
            int row = i4 >> 5;
            int c4  = (i4 & 31) << 2;
            float4 v = *(const float4*)(emb + (size_t)sidx[row] * DDIM + 128 * half + c4);
            rows[row * 129 + c4]     = v.x;
            rows[row * 129 + c4 + 1] = v.y;
            rows[row * 129 + c4 + 2] = v.z;
            rows[row * 129 + c4 + 3] = v.w;
        }
        __syncthreads();
#pragma unroll 8
        for (int pass = 0; pass < 16; ++pass) {
            int dl = pass * 8 + ds;
            int d  = 128 * half + dl;
            float q  = rows[j * 129 + dl];
            float zv = zt[d * 36 + j];
            float df = __fadd_rn(q, -zv);
            op[(size_t)d * HW] = __fadd_rn(zv, df);
            s = fmaf(df, df, s);
        }
    }

    // loss partial: warp shuffle + 8-slot smem reduce (deterministic)
#pragma unroll
    for (int o = 16; o; o >>= 1) s += __shfl_down_sync(0xffffffffu, s, o);
    if ((tid & 31) == 0) red[tid >> 5] = s;
    __syncthreads();
    if (tid == 0) {
        float t = red[0];
#pragma unroll
        for (int q = 1; q < 8; ++q) t += red[q];
        g_partial[blockIdx.x] = t;
    }
}

// ---------------- kernel D: finalize loss ----------------
__global__ void finalize_kernel(float* __restrict__ out) {
    __shared__ float red[256];
    float s = 0.f;
#pragma unroll
    for (int r = 0; r < GATHER_BLOCKS / 256; ++r)
        s += g_partial[threadIdx.x + 256 * r];
    red[threadIdx.x] = s;
    __syncthreads();
#pragma unroll
    for (int o = 128; o; o >>= 1) {
        if (threadIdx.x < o) red[threadIdx.x] += red[threadIdx.x + o];
        __syncthreads();
    }
    if (threadIdx.x == 0) {
        float q = red[0] / (float)NZ;
        out[NZ] = __fadd_rn(q, 0.25f * q);
    }
}

extern "C" void kernel_launch(void* const* d_in, const int* in_sizes, int n_in,
                              void* d_out, int out_size) {
    const float* a0 = (const float*)d_in[0];
    const float* a1 = (const float*)d_in[1];
    const float* z;
    const float* emb;
    if (in_sizes[0] == NZ) { z = a0; emb = a1; }
    else                   { z = a1; emb = a0; }
    float* out = (float*)d_out;

    cudaFuncSetAttribute(prep_kernel,
                         cudaFuncAttributeMaxDynamicSharedMemorySize, PREP_SMEM);
    cudaFuncSetAttribute(vq_gemm_kernel,
                         cudaFuncAttributeMaxDynamicSharedMemorySize, SM_DYN);
    cudaFuncSetAttribute(fused_tail_kernel,
                         cudaFuncAttributeMaxDynamicSharedMemorySize, FUSED_SMEM);

    int write_idx = (out_size >= NZ + 1 + NN) ? 1 : 0;

    prep_kernel<<<GATHER_BLOCKS + KK / 8, 256, PREP_SMEM>>>(z, emb);
    vq_gemm_kernel<<<dim3(256, 8), 256, SM_DYN>>>();
    fused_tail_kernel<<<GATHER_BLOCKS, 256, FUSED_SMEM>>>(z, emb, out, write_idx);
    if (out_size > NZ) finalize_kernel<<<1, 256>>>(out);
}